// round 1
// baseline (speedup 1.0000x reference)
#include <cuda_runtime.h>
#include <cstddef>

// Problem constants
#define Bn   4
#define Nn   8192
#define Cn   512
#define Hn   4
#define DHn  128
// qkv channel-major rows per batch: 3*C = 1536, m = s*512 + h*128 + c

// ---------------- scratch (device globals; no allocation allowed) ----------
__device__ float g_qkv [(size_t)Bn * 1536 * Nn];      // 192 MB, channel-major qkv
__device__ float g_inv [Bn * 1024];                   // 1/max(||q_c||,eps), 1/max(||k_d||,eps)
__device__ float g_attnP[16 * 32 * DHn * DHn];        // split-K partials (32 MB)
__device__ float g_attn [16 * DHn * DHn];             // softmaxed attention
__device__ float g_xca [(size_t)Bn * Nn * Cn];        // attn @ v, [B,N,C] layout (64 MB)

// ---------------------------------------------------------------------------
// Shared tile body: C[m0..+128, n0..+128] += A[m,:K] dot B[n,:K]  (A@B^T form,
// both operands K-contiguous). 256 threads, 8x8 accum per thread, BK=16.
// ---------------------------------------------------------------------------
__device__ __forceinline__ void gemm_tile_abt(
    const float* __restrict__ A, const float* __restrict__ B,
    float* __restrict__ C, const float* __restrict__ bias,
    int K, int lda, int ldb, int ldc, int m0, int n0)
{
    __shared__ float As[16][128];
    __shared__ float Bs[16][128];
    const int tid = threadIdx.x;
    const int tx  = tid & 15;
    const int ty  = tid >> 4;
    const int lm  = tid >> 1;          // 0..127 tile row
    const int lk  = (tid & 1) * 8;     // 0 or 8 within BK

    float acc[8][8];
#pragma unroll
    for (int i = 0; i < 8; i++)
#pragma unroll
        for (int j = 0; j < 8; j++) acc[i][j] = 0.f;

    const float* Aload = A + (size_t)(m0 + lm) * lda + lk;
    const float* Bload = B + (size_t)(n0 + lm) * ldb + lk;

    for (int k0 = 0; k0 < K; k0 += 16) {
        float4 a0 = *(const float4*)(Aload + k0);
        float4 a1 = *(const float4*)(Aload + k0 + 4);
        float4 b0 = *(const float4*)(Bload + k0);
        float4 b1 = *(const float4*)(Bload + k0 + 4);
        __syncthreads();
        As[lk+0][lm]=a0.x; As[lk+1][lm]=a0.y; As[lk+2][lm]=a0.z; As[lk+3][lm]=a0.w;
        As[lk+4][lm]=a1.x; As[lk+5][lm]=a1.y; As[lk+6][lm]=a1.z; As[lk+7][lm]=a1.w;
        Bs[lk+0][lm]=b0.x; Bs[lk+1][lm]=b0.y; Bs[lk+2][lm]=b0.z; Bs[lk+3][lm]=b0.w;
        Bs[lk+4][lm]=b1.x; Bs[lk+5][lm]=b1.y; Bs[lk+6][lm]=b1.z; Bs[lk+7][lm]=b1.w;
        __syncthreads();
#pragma unroll
        for (int kk = 0; kk < 16; kk++) {
            float a[8], bf[8];
            *(float4*)&a[0]  = *(const float4*)&As[kk][ty * 8];
            *(float4*)&a[4]  = *(const float4*)&As[kk][ty * 8 + 4];
            *(float4*)&bf[0] = *(const float4*)&Bs[kk][tx * 8];
            *(float4*)&bf[4] = *(const float4*)&Bs[kk][tx * 8 + 4];
#pragma unroll
            for (int i = 0; i < 8; i++)
#pragma unroll
                for (int j = 0; j < 8; j++)
                    acc[i][j] = fmaf(a[i], bf[j], acc[i][j]);
        }
    }

    float bv[8];
#pragma unroll
    for (int j = 0; j < 8; j++) bv[j] = bias ? bias[n0 + tx * 8 + j] : 0.f;
#pragma unroll
    for (int i = 0; i < 8; i++) {
        float* crow = C + (size_t)(m0 + ty * 8 + i) * ldc + n0 + tx * 8;
        float4 o0 = make_float4(acc[i][0]+bv[0], acc[i][1]+bv[1],
                                acc[i][2]+bv[2], acc[i][3]+bv[3]);
        float4 o1 = make_float4(acc[i][4]+bv[4], acc[i][5]+bv[5],
                                acc[i][6]+bv[6], acc[i][7]+bv[7]);
        *(float4*)crow       = o0;
        *(float4*)(crow + 4) = o1;
    }
}

// Generic batched A@B^T GEMM (used for QKV GEMM and output GEMM)
__global__ void __launch_bounds__(256) gemm_abt(
    const float* __restrict__ A, const float* __restrict__ B,
    float* __restrict__ C, const float* __restrict__ bias,
    int K, int lda, int ldb, int ldc,
    long long sA, long long sB, long long sC)
{
    A += (long long)blockIdx.z * sA;
    B += (long long)blockIdx.z * sB;
    C += (long long)blockIdx.z * sC;
    gemm_tile_abt(A, B, C, bias, K, lda, ldb, ldc,
                  blockIdx.y * 128, blockIdx.x * 128);
}

// ---------------------------------------------------------------------------
// Per-channel inverse L2 norms over N for q and k rows (m in [0,1024) of each
// batch's channel-major qkv block). grid = 4*1024 blocks, 256 threads.
// ---------------------------------------------------------------------------
__global__ void __launch_bounds__(256) norm_kernel()
{
    const int b = blockIdx.x >> 10;
    const int m = blockIdx.x & 1023;
    const float4* row = (const float4*)(g_qkv + ((size_t)b * 1536 + m) * Nn);
    float ss = 0.f;
    for (int i = threadIdx.x; i < Nn / 4; i += 256) {
        float4 v = row[i];
        ss = fmaf(v.x, v.x, ss);
        ss = fmaf(v.y, v.y, ss);
        ss = fmaf(v.z, v.z, ss);
        ss = fmaf(v.w, v.w, ss);
    }
    __shared__ float red[256];
    red[threadIdx.x] = ss;
    __syncthreads();
    for (int off = 128; off; off >>= 1) {
        if (threadIdx.x < off) red[threadIdx.x] += red[threadIdx.x + off];
        __syncthreads();
    }
    if (threadIdx.x == 0)
        g_inv[b * 1024 + m] = 1.f / fmaxf(sqrtf(red[0]), 1e-12f);
}

// ---------------------------------------------------------------------------
// Split-K partial q@k^T: per (b,h) a 128x128 output reduced over N=8192, split
// into 32 chunks of 256. grid = (32 chunks, 16 bh), 256 threads.
// ---------------------------------------------------------------------------
__global__ void __launch_bounds__(256) qk_partial_kernel()
{
    const int bh = blockIdx.y;
    const int b  = bh >> 2, h = bh & 3;
    const int k0base = blockIdx.x * 256;
    const float* qb = g_qkv + ((size_t)b * 1536 + h * DHn) * Nn + k0base;
    const float* kb = g_qkv + ((size_t)b * 1536 + 512 + h * DHn) * Nn + k0base;
    float* Cb = g_attnP + ((size_t)bh * 32 + blockIdx.x) * (DHn * DHn);
    gemm_tile_abt(qb, kb, Cb, nullptr, 256, Nn, Nn, DHn, 0, 0);
}

// ---------------------------------------------------------------------------
// Reduce split-K partials + apply q/k inverse norms + temperature + softmax
// over d. grid = 16*128 blocks (one per (bh, c) row), 128 threads (one per d).
// ---------------------------------------------------------------------------
__global__ void __launch_bounds__(128) softmax_kernel(const float* __restrict__ temp)
{
    const int bh = blockIdx.x >> 7;
    const int c  = blockIdx.x & 127;
    const int b  = bh >> 2, h = bh & 3;
    const int d  = threadIdx.x;

    const float* base = g_attnP + (size_t)bh * 32 * (DHn * DHn) + c * DHn + d;
    float s = 0.f;
#pragma unroll
    for (int p = 0; p < 32; p++) s += base[(size_t)p * (DHn * DHn)];

    const float qinv = g_inv[b * 1024 + h * DHn + c];
    const float kinv = g_inv[b * 1024 + 512 + h * DHn + d];
    const float val  = s * qinv * kinv * temp[h];

    __shared__ float red[128];
    red[d] = val;
    __syncthreads();
    for (int off = 64; off; off >>= 1) {
        if (d < off) red[d] = fmaxf(red[d], red[d + off]);
        __syncthreads();
    }
    const float mx = red[0];
    __syncthreads();
    const float e = expf(val - mx);
    red[d] = e;
    __syncthreads();
    for (int off = 64; off; off >>= 1) {
        if (d < off) red[d] += red[d + off];
        __syncthreads();
    }
    g_attn[(size_t)bh * (DHn * DHn) + c * DHn + d] = e / red[0];
}

// ---------------------------------------------------------------------------
// x_ca = attn @ v, written directly into [B,N,C] layout:
//   g_xca[b][n][h*128+c] = sum_d attn[bh][c][d] * v[bh][d][n]
// Tile: 128 n-rows x 128 c-cols per CTA; coalesced float4 writes along c.
// grid = (64 n-tiles, 16 bh), 256 threads, 8x8 per thread.
// ---------------------------------------------------------------------------
__global__ void __launch_bounds__(256) attn_v_kernel()
{
    const int bh = blockIdx.y;
    const int b  = bh >> 2, h = bh & 3;
    const int n0 = blockIdx.x * 128;
    const float* vbase = g_qkv + ((size_t)b * 1536 + 1024 + h * DHn) * Nn;
    const float* abase = g_attn + (size_t)bh * (DHn * DHn);

    __shared__ float Vs[16][128];   // [dd][n]
    __shared__ float Ts[16][128];   // [dd][c]  (attn transposed)

    const int tid = threadIdx.x;
    const int tx  = tid & 15;       // c-group
    const int ty  = tid >> 4;       // n-group
    const int lc  = tid >> 1;       // attn loader: c row
    const int ldk = (tid & 1) * 8;  // attn loader: d offset
    const int vr  = tid >> 4;       // v loader: dd row
    const int vn  = (tid & 15) * 8; // v loader: n offset

    float acc[8][8];
#pragma unroll
    for (int i = 0; i < 8; i++)
#pragma unroll
        for (int j = 0; j < 8; j++) acc[i][j] = 0.f;

    for (int d0 = 0; d0 < 128; d0 += 16) {
        float4 t0 = *(const float4*)(abase + (size_t)lc * DHn + d0 + ldk);
        float4 t1 = *(const float4*)(abase + (size_t)lc * DHn + d0 + ldk + 4);
        float4 v0 = *(const float4*)(vbase + (size_t)(d0 + vr) * Nn + n0 + vn);
        float4 v1 = *(const float4*)(vbase + (size_t)(d0 + vr) * Nn + n0 + vn + 4);
        __syncthreads();
        Ts[ldk+0][lc]=t0.x; Ts[ldk+1][lc]=t0.y; Ts[ldk+2][lc]=t0.z; Ts[ldk+3][lc]=t0.w;
        Ts[ldk+4][lc]=t1.x; Ts[ldk+5][lc]=t1.y; Ts[ldk+6][lc]=t1.z; Ts[ldk+7][lc]=t1.w;
        *(float4*)&Vs[vr][vn]     = v0;
        *(float4*)&Vs[vr][vn + 4] = v1;
        __syncthreads();
#pragma unroll
        for (int dd = 0; dd < 16; dd++) {
            float a[8], cf[8];
            *(float4*)&a[0]  = *(const float4*)&Vs[dd][ty * 8];
            *(float4*)&a[4]  = *(const float4*)&Vs[dd][ty * 8 + 4];
            *(float4*)&cf[0] = *(const float4*)&Ts[dd][tx * 8];
            *(float4*)&cf[4] = *(const float4*)&Ts[dd][tx * 8 + 4];
#pragma unroll
            for (int i = 0; i < 8; i++)
#pragma unroll
                for (int j = 0; j < 8; j++)
                    acc[i][j] = fmaf(a[i], cf[j], acc[i][j]);
        }
    }

#pragma unroll
    for (int i = 0; i < 8; i++) {
        float* o = g_xca + ((size_t)b * Nn + n0 + ty * 8 + i) * Cn + h * DHn + tx * 8;
        *(float4*)o       = make_float4(acc[i][0], acc[i][1], acc[i][2], acc[i][3]);
        *(float4*)(o + 4) = make_float4(acc[i][4], acc[i][5], acc[i][6], acc[i][7]);
    }
}

// ---------------------------------------------------------------------------
extern "C" void kernel_launch(void* const* d_in, const int* in_sizes, int n_in,
                              void* d_out, int out_size)
{
    const float* x    = (const float*)d_in[0];   // [4,8192,512]
    const float* Wqkv = (const float*)d_in[1];   // [1536,512]
    const float* Wout = (const float*)d_in[2];   // [512,512]
    const float* bout = (const float*)d_in[3];   // [512]
    const float* temp = (const float*)d_in[4];   // [4,1,1]
    float* out = (float*)d_out;                  // [4,8192,512]

    float *qkv, *xca;
    cudaGetSymbolAddress((void**)&qkv, g_qkv);
    cudaGetSymbolAddress((void**)&xca, g_xca);

    // 1. QKV GEMM, fused transpose to channel-major: qkv[b][m][n] = W_qkv[m,:] . x[b][n,:]
    gemm_abt<<<dim3(64, 12, 4), 256>>>(
        Wqkv, x, qkv, nullptr,
        /*K=*/512, /*lda=*/512, /*ldb=*/512, /*ldc=*/Nn,
        /*sA=*/0LL, /*sB=*/(long long)Nn * Cn, /*sC=*/(long long)1536 * Nn);

    // 2. inverse L2 norms for q,k channels
    norm_kernel<<<Bn * 1024, 256>>>();

    // 3. split-K q@k^T partials
    qk_partial_kernel<<<dim3(32, 16), 256>>>();

    // 4. reduce + normalize-scale + temperature + softmax
    softmax_kernel<<<16 * 128, 128>>>(temp);

    // 5. x_ca = attn @ v into [B,N,C]
    attn_v_kernel<<<dim3(64, 16), 256>>>();

    // 6. out = x_ca @ W_out^T + b_out
    gemm_abt<<<dim3(4, 256, 1), 256>>>(
        xca, Wout, out, bout,
        /*K=*/512, /*lda=*/512, /*ldb=*/512, /*ldc=*/512,
        0LL, 0LL, 0LL);
}

// round 2
// speedup vs baseline: 1.1056x; 1.1056x over previous
#include <cuda_runtime.h>
#include <mma.h>
#include <cstddef>

using namespace nvcuda;

// Problem constants
#define Bn   4
#define Nn   8192
#define Cn   512
#define Hn   4
#define DHn  128
#define QK_SPLIT 16              // split-K chunks for q@k^T (each K=512)

// ---------------- scratch (device globals; no allocation allowed) ----------
__device__ float g_qkv [(size_t)Bn * 1536 * Nn];            // 192 MB channel-major qkv
__device__ float g_inv [Bn * 1024];                          // inverse L2 norms (q,k)
__device__ float g_attnP[16 * QK_SPLIT * DHn * DHn];         // split-K partials (16 MB)
__device__ float g_attn [16 * DHn * DHn];                    // softmaxed attention
__device__ float g_xca [(size_t)Bn * Nn * Cn];               // attn @ v, [B,N,C] (64 MB)

// ---------------------------------------------------------------------------
// TF32 WMMA tile: C[m0..+128, n0..+128] = A[m,:K] . B[n,:K]   (A@B^T, both
// operands K-contiguous). 256 threads = 8 warps, warp tile 32x64, BK=32.
// ---------------------------------------------------------------------------
__device__ __forceinline__ void wmma_tile_abt(
    const float* __restrict__ A, const float* __restrict__ B,
    float* __restrict__ C,
    int K, int lda, int ldb, int ldc, int m0, int n0)
{
    __shared__ float As[128][40];
    __shared__ float Bs[128][40];

    const int tid = threadIdx.x;
    const int wid = tid >> 5;
    const int wm  = (wid & 3) * 32;     // warp m offset within tile
    const int wn  = (wid >> 2) * 64;    // warp n offset within tile
    const int lm  = tid >> 1;           // loader row 0..127
    const int lk  = (tid & 1) * 16;     // loader k offset {0,16}

    wmma::fragment<wmma::accumulator, 16, 16, 8, float> acc[2][4];
#pragma unroll
    for (int i = 0; i < 2; i++)
#pragma unroll
        for (int j = 0; j < 4; j++) wmma::fill_fragment(acc[i][j], 0.f);

    const float* Aload = A + (size_t)(m0 + lm) * lda + lk;
    const float* Bload = B + (size_t)(n0 + lm) * ldb + lk;

    for (int k0 = 0; k0 < K; k0 += 32) {
        float4 a0 = *(const float4*)(Aload + k0);
        float4 a1 = *(const float4*)(Aload + k0 + 4);
        float4 a2 = *(const float4*)(Aload + k0 + 8);
        float4 a3 = *(const float4*)(Aload + k0 + 12);
        float4 b0 = *(const float4*)(Bload + k0);
        float4 b1 = *(const float4*)(Bload + k0 + 4);
        float4 b2 = *(const float4*)(Bload + k0 + 8);
        float4 b3 = *(const float4*)(Bload + k0 + 12);
        __syncthreads();
        *(float4*)&As[lm][lk]      = a0;
        *(float4*)&As[lm][lk + 4]  = a1;
        *(float4*)&As[lm][lk + 8]  = a2;
        *(float4*)&As[lm][lk + 12] = a3;
        *(float4*)&Bs[lm][lk]      = b0;
        *(float4*)&Bs[lm][lk + 4]  = b1;
        *(float4*)&Bs[lm][lk + 8]  = b2;
        *(float4*)&Bs[lm][lk + 12] = b3;
        __syncthreads();

#pragma unroll
        for (int kk = 0; kk < 4; kk++) {
            wmma::fragment<wmma::matrix_a, 16, 16, 8, wmma::precision::tf32,
                           wmma::row_major> af[2];
            wmma::fragment<wmma::matrix_b, 16, 16, 8, wmma::precision::tf32,
                           wmma::col_major> bf[4];
#pragma unroll
            for (int i = 0; i < 2; i++) {
                wmma::load_matrix_sync(af[i], &As[wm + i * 16][kk * 8], 40);
#pragma unroll
                for (int t = 0; t < af[i].num_elements; t++)
                    af[i].x[t] = wmma::__float_to_tf32(af[i].x[t]);
            }
#pragma unroll
            for (int j = 0; j < 4; j++) {
                wmma::load_matrix_sync(bf[j], &Bs[wn + j * 16][kk * 8], 40);
#pragma unroll
                for (int t = 0; t < bf[j].num_elements; t++)
                    bf[j].x[t] = wmma::__float_to_tf32(bf[j].x[t]);
            }
#pragma unroll
            for (int i = 0; i < 2; i++)
#pragma unroll
                for (int j = 0; j < 4; j++)
                    wmma::mma_sync(acc[i][j], af[i], bf[j], acc[i][j]);
        }
    }

#pragma unroll
    for (int i = 0; i < 2; i++)
#pragma unroll
        for (int j = 0; j < 4; j++)
            wmma::store_matrix_sync(
                C + (size_t)(m0 + wm + i * 16) * ldc + n0 + wn + j * 16,
                acc[i][j], ldc, wmma::mem_row_major);
}

// Generic batched A@B^T GEMM
__global__ void __launch_bounds__(256) wmma_abt(
    const float* __restrict__ A, const float* __restrict__ B,
    float* __restrict__ C,
    int K, int lda, int ldb, int ldc,
    long long sA, long long sB, long long sC)
{
    A += (long long)blockIdx.z * sA;
    B += (long long)blockIdx.z * sB;
    C += (long long)blockIdx.z * sC;
    wmma_tile_abt(A, B, C, K, lda, ldb, ldc, blockIdx.y * 128, blockIdx.x * 128);
}

// Split-K q@k^T partials: grid (QK_SPLIT chunks, 16 bh)
__global__ void __launch_bounds__(256) qk_partial_wmma()
{
    const int bh = blockIdx.y;
    const int b  = bh >> 2, h = bh & 3;
    const int k0base = blockIdx.x * (Nn / QK_SPLIT);
    const float* qb = g_qkv + ((size_t)b * 1536 + h * DHn) * Nn + k0base;
    const float* kb = g_qkv + ((size_t)b * 1536 + 512 + h * DHn) * Nn + k0base;
    float* Cb = g_attnP + ((size_t)bh * QK_SPLIT + blockIdx.x) * (DHn * DHn);
    wmma_tile_abt(qb, kb, Cb, Nn / QK_SPLIT, Nn, Nn, DHn, 0, 0);
}

// ---------------------------------------------------------------------------
// attn @ v (A@B form: A=attn[c][d] row-major, B=v[d][n] row-major), stored
// col-major directly into [B,N,C]. grid (64 n-tiles, 16 bh).
// ---------------------------------------------------------------------------
__global__ void __launch_bounds__(256) attn_v_wmma()
{
    const int bh = blockIdx.y;
    const int b  = bh >> 2, h = bh & 3;
    const int n0 = blockIdx.x * 128;
    const float* vbase = g_qkv + ((size_t)b * 1536 + 1024 + h * DHn) * Nn;
    const float* abase = g_attn + (size_t)bh * (DHn * DHn);

    __shared__ float As[128][40];    // attn rows c, k=d contiguous
    __shared__ float Vs[32][136];    // v rows k=d, n contiguous

    const int tid = threadIdx.x;
    const int wid = tid >> 5;
    const int wm  = (wid & 3) * 32;     // c offset
    const int wn  = (wid >> 2) * 64;    // n offset
    const int lm  = tid >> 1;           // attn loader row
    const int lk  = (tid & 1) * 16;
    const int vr  = tid >> 3;           // v loader row 0..31
    const int vc  = (tid & 7) * 16;     // v loader col offset

    wmma::fragment<wmma::accumulator, 16, 16, 8, float> acc[2][4];
#pragma unroll
    for (int i = 0; i < 2; i++)
#pragma unroll
        for (int j = 0; j < 4; j++) wmma::fill_fragment(acc[i][j], 0.f);

    for (int d0 = 0; d0 < 128; d0 += 32) {
        float4 a0 = *(const float4*)(abase + (size_t)lm * DHn + d0 + lk);
        float4 a1 = *(const float4*)(abase + (size_t)lm * DHn + d0 + lk + 4);
        float4 a2 = *(const float4*)(abase + (size_t)lm * DHn + d0 + lk + 8);
        float4 a3 = *(const float4*)(abase + (size_t)lm * DHn + d0 + lk + 12);
        float4 v0 = *(const float4*)(vbase + (size_t)(d0 + vr) * Nn + n0 + vc);
        float4 v1 = *(const float4*)(vbase + (size_t)(d0 + vr) * Nn + n0 + vc + 4);
        float4 v2 = *(const float4*)(vbase + (size_t)(d0 + vr) * Nn + n0 + vc + 8);
        float4 v3 = *(const float4*)(vbase + (size_t)(d0 + vr) * Nn + n0 + vc + 12);
        __syncthreads();
        *(float4*)&As[lm][lk]      = a0;
        *(float4*)&As[lm][lk + 4]  = a1;
        *(float4*)&As[lm][lk + 8]  = a2;
        *(float4*)&As[lm][lk + 12] = a3;
        *(float4*)&Vs[vr][vc]      = v0;
        *(float4*)&Vs[vr][vc + 4]  = v1;
        *(float4*)&Vs[vr][vc + 8]  = v2;
        *(float4*)&Vs[vr][vc + 12] = v3;
        __syncthreads();

#pragma unroll
        for (int kk = 0; kk < 4; kk++) {
            wmma::fragment<wmma::matrix_a, 16, 16, 8, wmma::precision::tf32,
                           wmma::row_major> af[2];
            wmma::fragment<wmma::matrix_b, 16, 16, 8, wmma::precision::tf32,
                           wmma::row_major> bf[4];
#pragma unroll
            for (int i = 0; i < 2; i++) {
                wmma::load_matrix_sync(af[i], &As[wm + i * 16][kk * 8], 40);
#pragma unroll
                for (int t = 0; t < af[i].num_elements; t++)
                    af[i].x[t] = wmma::__float_to_tf32(af[i].x[t]);
            }
#pragma unroll
            for (int j = 0; j < 4; j++) {
                wmma::load_matrix_sync(bf[j], &Vs[kk * 8][wn + j * 16], 136);
#pragma unroll
                for (int t = 0; t < bf[j].num_elements; t++)
                    bf[j].x[t] = wmma::__float_to_tf32(bf[j].x[t]);
            }
#pragma unroll
            for (int i = 0; i < 2; i++)
#pragma unroll
                for (int j = 0; j < 4; j++)
                    wmma::mma_sync(acc[i][j], af[i], bf[j], acc[i][j]);
        }
    }

    // store transposed: element (c_local, n_local) -> xca[n][c], c contiguous
#pragma unroll
    for (int i = 0; i < 2; i++)
#pragma unroll
        for (int j = 0; j < 4; j++) {
            float* p = g_xca + ((size_t)b * Nn + n0 + wn + j * 16) * Cn
                             + h * DHn + wm + i * 16;
            wmma::store_matrix_sync(p, acc[i][j], Cn, wmma::mem_col_major);
        }
}

// ---------------------------------------------------------------------------
// Per-channel inverse L2 norms over N for q,k rows.
// ---------------------------------------------------------------------------
__global__ void __launch_bounds__(256) norm_kernel()
{
    const int b = blockIdx.x >> 10;
    const int m = blockIdx.x & 1023;
    const float4* row = (const float4*)(g_qkv + ((size_t)b * 1536 + m) * Nn);
    float ss = 0.f;
    for (int i = threadIdx.x; i < Nn / 4; i += 256) {
        float4 v = row[i];
        ss = fmaf(v.x, v.x, ss);
        ss = fmaf(v.y, v.y, ss);
        ss = fmaf(v.z, v.z, ss);
        ss = fmaf(v.w, v.w, ss);
    }
    __shared__ float red[256];
    red[threadIdx.x] = ss;
    __syncthreads();
    for (int off = 128; off; off >>= 1) {
        if (threadIdx.x < off) red[threadIdx.x] += red[threadIdx.x + off];
        __syncthreads();
    }
    if (threadIdx.x == 0)
        g_inv[b * 1024 + m] = 1.f / fmaxf(sqrtf(red[0]), 1e-12f);
}

// ---------------------------------------------------------------------------
// Reduce split-K partials + norms + temperature + softmax over d.
// ---------------------------------------------------------------------------
__global__ void __launch_bounds__(128) softmax_kernel(const float* __restrict__ temp)
{
    const int bh = blockIdx.x >> 7;
    const int c  = blockIdx.x & 127;
    const int b  = bh >> 2, h = bh & 3;
    const int d  = threadIdx.x;

    const float* base = g_attnP + (size_t)bh * QK_SPLIT * (DHn * DHn) + c * DHn + d;
    float s = 0.f;
#pragma unroll
    for (int p = 0; p < QK_SPLIT; p++) s += base[(size_t)p * (DHn * DHn)];

    const float qinv = g_inv[b * 1024 + h * DHn + c];
    const float kinv = g_inv[b * 1024 + 512 + h * DHn + d];
    const float val  = s * qinv * kinv * temp[h];

    __shared__ float red[128];
    red[d] = val;
    __syncthreads();
    for (int off = 64; off; off >>= 1) {
        if (d < off) red[d] = fmaxf(red[d], red[d + off]);
        __syncthreads();
    }
    const float mx = red[0];
    __syncthreads();
    const float e = expf(val - mx);
    red[d] = e;
    __syncthreads();
    for (int off = 64; off; off >>= 1) {
        if (d < off) red[d] += red[d + off];
        __syncthreads();
    }
    g_attn[(size_t)bh * (DHn * DHn) + c * DHn + d] = e / red[0];
}

// ---------------------------------------------------------------------------
// out += bias (broadcast over last dim of 512)
// ---------------------------------------------------------------------------
__global__ void __launch_bounds__(256) bias_add(float* __restrict__ out,
                                                const float* __restrict__ bias)
{
    const size_t i = (size_t)blockIdx.x * 256 + threadIdx.x;  // float4 index
    float4 v = ((float4*)out)[i];
    const float4 bb = ((const float4*)bias)[i & 127];
    v.x += bb.x; v.y += bb.y; v.z += bb.z; v.w += bb.w;
    ((float4*)out)[i] = v;
}

// ---------------------------------------------------------------------------
extern "C" void kernel_launch(void* const* d_in, const int* in_sizes, int n_in,
                              void* d_out, int out_size)
{
    const float* x    = (const float*)d_in[0];   // [4,8192,512]
    const float* Wqkv = (const float*)d_in[1];   // [1536,512]
    const float* Wout = (const float*)d_in[2];   // [512,512]
    const float* bout = (const float*)d_in[3];   // [512]
    const float* temp = (const float*)d_in[4];   // [4,1,1]
    float* out = (float*)d_out;                  // [4,8192,512]

    float *qkv, *xca;
    cudaGetSymbolAddress((void**)&qkv, g_qkv);
    cudaGetSymbolAddress((void**)&xca, g_xca);

    // 1. QKV GEMM, fused transpose: qkv[b][m][n] = W_qkv[m,:] . x[b][n,:]
    wmma_abt<<<dim3(64, 12, 4), 256>>>(
        Wqkv, x, qkv,
        /*K=*/512, /*lda=*/512, /*ldb=*/512, /*ldc=*/Nn,
        /*sA=*/0LL, /*sB=*/(long long)Nn * Cn, /*sC=*/(long long)1536 * Nn);

    // 2. inverse L2 norms for q,k channels
    norm_kernel<<<Bn * 1024, 256>>>();

    // 3. split-K q@k^T partials (tensor core)
    qk_partial_wmma<<<dim3(QK_SPLIT, 16), 256>>>();

    // 4. reduce + scale + softmax
    softmax_kernel<<<16 * 128, 128>>>(temp);

    // 5. x_ca = attn @ v into [B,N,C] (tensor core)
    attn_v_wmma<<<dim3(64, 16), 256>>>();

    // 6. out = x_ca @ W_out^T (tensor core), then + b_out
    wmma_abt<<<dim3(4, 256, 1), 256>>>(
        xca, Wout, out,
        /*K=*/512, /*lda=*/512, /*ldb=*/512, /*ldc=*/512,
        0LL, 0LL, 0LL);
    bias_add<<<(Bn * Nn * Cn / 4) / 256, 256>>>(out, bout);
}

// round 3
// speedup vs baseline: 4.6937x; 4.2454x over previous
#include <cuda_runtime.h>
#include <cuda_fp16.h>
#include <cstddef>
#include <cstdint>

#define Bn   4
#define Nn   8192
#define Cn   512
#define DHn  128
#define QK_SPLIT 16

// ---------------- scratch (device globals) ---------------------------------
__device__ __align__(128) __half g_xh  [(size_t)Bn * Nn * Cn];     // x in fp16 (32MB)
__device__ __align__(128) __half g_wqh [1536 * 512];
__device__ __align__(128) __half g_woh [512 * 512];
__device__ __align__(128) __half g_qkv [(size_t)Bn * 1536 * Nn];   // channel-major (96MB)
__device__ __align__(128) __half g_vt  [(size_t)Bn * Nn * Cn];     // v token-major (32MB)
__device__ __align__(128) float  g_inv [Bn * 1024];
__device__ __align__(128) float  g_attnP[16 * QK_SPLIT * DHn * DHn];
__device__ __align__(128) __half g_attn [16 * DHn * DHn];
__device__ __align__(128) __half g_xca [(size_t)Bn * Nn * Cn];     // (32MB)

// ---------------- PTX helpers ----------------------------------------------
__device__ __forceinline__ uint32_t sptr(const void* p) {
    return (uint32_t)__cvta_generic_to_shared(p);
}
#define CPA(dst, src) asm volatile("cp.async.ca.shared.global [%0],[%1],16;\n" \
                                   :: "r"(dst), "l"(src))
#define CPC() asm volatile("cp.async.commit_group;\n")
#define CPW0() asm volatile("cp.async.wait_group 0;\n")
#define CPW1() asm volatile("cp.async.wait_group 1;\n")

__device__ __forceinline__ void ldmx4(uint32_t* r, uint32_t a) {
    asm volatile("ldmatrix.sync.aligned.m8n8.x4.shared.b16 {%0,%1,%2,%3},[%4];"
                 : "=r"(r[0]), "=r"(r[1]), "=r"(r[2]), "=r"(r[3]) : "r"(a));
}
__device__ __forceinline__ void ldmx2(uint32_t* r, uint32_t a) {
    asm volatile("ldmatrix.sync.aligned.m8n8.x2.shared.b16 {%0,%1},[%2];"
                 : "=r"(r[0]), "=r"(r[1]) : "r"(a));
}
__device__ __forceinline__ void mma16816(float* c, const uint32_t* a, const uint32_t* b) {
    asm volatile(
        "mma.sync.aligned.m16n8k16.row.col.f32.f16.f16.f32 "
        "{%0,%1,%2,%3},{%4,%5,%6,%7},{%8,%9},{%0,%1,%2,%3};"
        : "+f"(c[0]), "+f"(c[1]), "+f"(c[2]), "+f"(c[3])
        : "r"(a[0]), "r"(a[1]), "r"(a[2]), "r"(a[3]), "r"(b[0]), "r"(b[1]));
}

// ---------------------------------------------------------------------------
// fp16 A@B^T GEMM tile: C[m0..+128, n0..+128] = A[m,:K] . B[n,:K]
// Both operands K-contiguous fp16. 256 threads, 8 warps (64x32 warp tiles),
// BK=32, cp.async double buffered, fp32 accumulate.
// ---------------------------------------------------------------------------
template<bool HALF_OUT, bool BIAS>
__device__ __forceinline__ void gemm_abt_f16(
    const __half* __restrict__ A, const __half* __restrict__ B,
    void* __restrict__ Cp, const float* __restrict__ bias,
    int K, int lda, int ldb, int ldc, int m0, int n0)
{
    __shared__ __half As[2][128 * 40];
    __shared__ __half Bs[2][128 * 40];

    const int tid  = threadIdx.x;
    const int lane = tid & 31;
    const int wid  = tid >> 5;
    const int wm   = (wid & 1) * 64;
    const int wn   = (wid >> 1) * 32;
    const int lrow = tid >> 2;            // 0..63
    const int lcol = (tid & 3) * 8;       // 0,8,16,24 (halves)

    float acc[4][4][4];
#pragma unroll
    for (int i = 0; i < 4; i++)
#pragma unroll
        for (int j = 0; j < 4; j++)
#pragma unroll
            for (int t = 0; t < 4; t++) acc[i][j][t] = 0.f;

    const __half* Ag = A + (size_t)(m0 + lrow) * lda + lcol;
    const __half* Bg = B + (size_t)(n0 + lrow) * ldb + lcol;
    const uint32_t asb = sptr(&As[0][0]);
    const uint32_t bsb = sptr(&Bs[0][0]);
    const uint32_t so  = 128 * 40 * 2;    // stage byte offset

    auto load_stage = [&](int st, int k0) {
        uint32_t a = asb + st * so, b = bsb + st * so;
        CPA(a + (lrow * 40 + lcol) * 2,        Ag + k0);
        CPA(a + ((lrow + 64) * 40 + lcol) * 2, Ag + (size_t)64 * lda + k0);
        CPA(b + (lrow * 40 + lcol) * 2,        Bg + k0);
        CPA(b + ((lrow + 64) * 40 + lcol) * 2, Bg + (size_t)64 * ldb + k0);
        CPC();
    };
    load_stage(0, 0);

    // per-lane fragment base addresses (bytes)
    const uint32_t a_fb = ((wm + (lane & 15)) * 40 + (lane >> 4) * 8) * 2;
    const uint32_t b_fb = ((wn + (lane & 7)) * 40 + ((lane >> 3) & 1) * 8) * 2;

    const int niter = K / 32;
    int buf = 0;
    for (int it = 0; it < niter; ++it) {
        if (it + 1 < niter) { load_stage(buf ^ 1, (it + 1) * 32); CPW1(); }
        else                { CPW0(); }
        __syncthreads();

        const uint32_t ab = asb + buf * so + a_fb;
        const uint32_t bb = bsb + buf * so + b_fb;
#pragma unroll
        for (int ks = 0; ks < 2; ++ks) {
            uint32_t a[4][4], bf[4][2];
#pragma unroll
            for (int mi = 0; mi < 4; mi++)
                ldmx4(a[mi], ab + (mi * 16 * 40 + ks * 16) * 2);
#pragma unroll
            for (int nj = 0; nj < 4; nj++)
                ldmx2(bf[nj], bb + (nj * 8 * 40 + ks * 16) * 2);
#pragma unroll
            for (int mi = 0; mi < 4; mi++)
#pragma unroll
                for (int nj = 0; nj < 4; nj++)
                    mma16816(acc[mi][nj], a[mi], bf[nj]);
        }
        __syncthreads();
        buf ^= 1;
    }

    const int g  = lane >> 2;
    const int tg = lane & 3;
#pragma unroll
    for (int mi = 0; mi < 4; mi++) {
#pragma unroll
        for (int nj = 0; nj < 4; nj++) {
            const int r0 = m0 + wm + mi * 16 + g;
            const int cc = n0 + wn + nj * 8 + 2 * tg;
            float* a4 = acc[mi][nj];
            if (HALF_OUT) {
                __half* C = (__half*)Cp;
                *(__half2*)&C[(size_t)r0 * ldc + cc]       = __floats2half2_rn(a4[0], a4[1]);
                *(__half2*)&C[(size_t)(r0 + 8) * ldc + cc] = __floats2half2_rn(a4[2], a4[3]);
            } else {
                float* C = (float*)Cp;
                float b0 = 0.f, b1 = 0.f;
                if (BIAS) { float2 bb = *(const float2*)&bias[cc]; b0 = bb.x; b1 = bb.y; }
                *(float2*)&C[(size_t)r0 * ldc + cc]       = make_float2(a4[0] + b0, a4[1] + b1);
                *(float2*)&C[(size_t)(r0 + 8) * ldc + cc] = make_float2(a4[2] + b0, a4[3] + b1);
            }
        }
    }
}

// ---------------- GEMM kernel wrappers --------------------------------------
// 1. qkv[b][m][n] = Wqkv[m,:] . x[b][n,:]   (half out, channel-major)
__global__ void __launch_bounds__(256) k_qkv()
{
    const __half* B = g_xh + (size_t)blockIdx.z * Nn * Cn;
    __half* C = g_qkv + (size_t)blockIdx.z * 1536 * Nn;
    gemm_abt_f16<true, false>(g_wqh, B, C, nullptr, 512, 512, 512, Nn,
                              blockIdx.y * 128, blockIdx.x * 128);
}

// 3. split-K q@k^T partials (fp32 out)
__global__ void __launch_bounds__(256) k_qk()
{
    const int bh = blockIdx.y;
    const __half* qb = g_qkv + ((size_t)(bh >> 2) * 1536 + (bh & 3) * DHn) * Nn
                     + blockIdx.x * 512;
    const __half* kb = qb + (size_t)512 * Nn;
    float* C = g_attnP + ((size_t)bh * QK_SPLIT + blockIdx.x) * (DHn * DHn);
    gemm_abt_f16<false, false>(qb, kb, C, nullptr, 512, Nn, Nn, DHn, 0, 0);
}

// 5. xca[b][n][h*128+c] = sum_d v_t[b][n][h*128+d] * attn[bh][c][d]  (half out)
__global__ void __launch_bounds__(256) k_av()
{
    const int bh = blockIdx.z;
    const int b = bh >> 2, h = bh & 3;
    const __half* A  = g_vt  + (size_t)b * Nn * Cn + h * DHn;   // rows n, lda 512
    const __half* Bt = g_attn + (size_t)bh * DHn * DHn;          // rows c, ldb 128
    __half* C = g_xca + (size_t)b * Nn * Cn + h * DHn;           // [n][c] ldc 512
    gemm_abt_f16<true, false>(A, Bt, C, nullptr, 128, 512, 128, 512,
                              blockIdx.y * 128, 0);
}

// 6. out = xca @ Wout^T + bias   (fp32 out)
__global__ void __launch_bounds__(256) k_out(float* __restrict__ out,
                                             const float* __restrict__ bias)
{
    gemm_abt_f16<false, true>(g_xca, g_woh, out, bias, 512, 512, 512, 512,
                              blockIdx.y * 128, blockIdx.x * 128);
}

// ---------------- small kernels ---------------------------------------------
__global__ void __launch_bounds__(256) f2h(const float* __restrict__ s,
                                           __half* __restrict__ d, int n4)
{
    const int i = blockIdx.x * 256 + threadIdx.x;
    if (i < n4) {
        float4 v = ((const float4*)s)[i];
        ((__half2*)d)[i * 2]     = __floats2half2_rn(v.x, v.y);
        ((__half2*)d)[i * 2 + 1] = __floats2half2_rn(v.z, v.w);
    }
}

// per-channel inverse L2 norms over N for q,k rows (half input)
__global__ void __launch_bounds__(256) norm_kernel()
{
    const int b = blockIdx.x >> 10;
    const int m = blockIdx.x & 1023;
    const __half2* row = (const __half2*)(g_qkv + ((size_t)b * 1536 + m) * Nn);
    float ss = 0.f;
    for (int i = threadIdx.x; i < Nn / 2; i += 256) {
        float2 f = __half22float2(row[i]);
        ss = fmaf(f.x, f.x, fmaf(f.y, f.y, ss));
    }
    __shared__ float red[256];
    red[threadIdx.x] = ss;
    __syncthreads();
    for (int off = 128; off; off >>= 1) {
        if (threadIdx.x < off) red[threadIdx.x] += red[threadIdx.x + off];
        __syncthreads();
    }
    if (threadIdx.x == 0)
        g_inv[b * 1024 + m] = 1.f / fmaxf(sqrtf(red[0]), 1e-12f);
}

// v transpose: g_vt[b][n][hd] = g_qkv[b][1024+hd][n]
__global__ void __launch_bounds__(256) vtrans()
{
    __shared__ __half ts[32][33];
    const int n0 = blockIdx.x * 32, hd0 = blockIdx.y * 32, b = blockIdx.z;
    const int tx = threadIdx.x, ty = threadIdx.y;
    const __half* src = g_qkv + ((size_t)b * 1536 + 1024 + hd0) * Nn + n0;
#pragma unroll
    for (int r = 0; r < 4; r++)
        ts[ty + r * 8][tx] = src[(size_t)(ty + r * 8) * Nn + tx];
    __syncthreads();
    __half* dst = g_vt + ((size_t)b * Nn + n0) * Cn + hd0;
#pragma unroll
    for (int r = 0; r < 4; r++)
        dst[(size_t)(ty + r * 8) * Cn + tx] = ts[tx][ty + r * 8];
}

// reduce split-K partials + norms + temperature + softmax; half output
__global__ void __launch_bounds__(128) softmax_kernel(const float* __restrict__ temp)
{
    const int bh = blockIdx.x >> 7;
    const int c  = blockIdx.x & 127;
    const int b  = bh >> 2, h = bh & 3;
    const int d  = threadIdx.x;

    const float* base = g_attnP + (size_t)bh * QK_SPLIT * (DHn * DHn) + c * DHn + d;
    float s = 0.f;
#pragma unroll
    for (int p = 0; p < QK_SPLIT; p++) s += base[(size_t)p * (DHn * DHn)];

    const float qinv = g_inv[b * 1024 + h * DHn + c];
    const float kinv = g_inv[b * 1024 + 512 + h * DHn + d];
    const float val  = s * qinv * kinv * temp[h];

    __shared__ float red[128];
    red[d] = val;
    __syncthreads();
    for (int off = 64; off; off >>= 1) {
        if (d < off) red[d] = fmaxf(red[d], red[d + off]);
        __syncthreads();
    }
    const float mx = red[0];
    __syncthreads();
    const float e = expf(val - mx);
    red[d] = e;
    __syncthreads();
    for (int off = 64; off; off >>= 1) {
        if (d < off) red[d] += red[d + off];
        __syncthreads();
    }
    g_attn[(size_t)bh * (DHn * DHn) + c * DHn + d] = __float2half_rn(e / red[0]);
}

// ---------------------------------------------------------------------------
extern "C" void kernel_launch(void* const* d_in, const int* in_sizes, int n_in,
                              void* d_out, int out_size)
{
    const float* x    = (const float*)d_in[0];   // [4,8192,512]
    const float* Wqkv = (const float*)d_in[1];   // [1536,512]
    const float* Wout = (const float*)d_in[2];   // [512,512]
    const float* bout = (const float*)d_in[3];   // [512]
    const float* temp = (const float*)d_in[4];   // [4,1,1]
    float* out = (float*)d_out;                  // [4,8192,512]

    __half *xh, *wqh, *woh;
    cudaGetSymbolAddress((void**)&xh,  g_xh);
    cudaGetSymbolAddress((void**)&wqh, g_wqh);
    cudaGetSymbolAddress((void**)&woh, g_woh);

    // 0. fp32 -> fp16 conversions
    f2h<<<(Bn * Nn * Cn / 4 + 255) / 256, 256>>>(x, xh, Bn * Nn * Cn / 4);
    f2h<<<(1536 * 512 / 4 + 255) / 256, 256>>>(Wqkv, wqh, 1536 * 512 / 4);
    f2h<<<(512 * 512 / 4 + 255) / 256, 256>>>(Wout, woh, 512 * 512 / 4);

    // 1. QKV GEMM (fp16 tensor core), channel-major output
    k_qkv<<<dim3(64, 12, 4), 256>>>();

    // 2. inverse L2 norms
    norm_kernel<<<Bn * 1024, 256>>>();

    // 2b. v transpose to token-major
    vtrans<<<dim3(Nn / 32, 16, Bn), dim3(32, 8)>>>();

    // 3. split-K q@k^T partials
    k_qk<<<dim3(QK_SPLIT, 16), 256>>>();

    // 4. reduce + scale + softmax
    softmax_kernel<<<16 * 128, 128>>>(temp);

    // 5. xca = attn @ v (token-major output)
    k_av<<<dim3(1, 64, 16), 256>>>();

    // 6. out = xca @ Wout^T + bias
    k_out<<<dim3(4, 256), 256>>>(out, bout);
}